// round 4
// baseline (speedup 1.0000x reference)
#include <cuda_runtime.h>

#define B   8
#define C   1024
#define HW  4096
#define K   16

// Scratch (no allocations allowed) — fully rewritten every launch, so graph
// replay is deterministic.
__device__ float g_num[B * K * C];      // masked class sums
__device__ float g_protoN[B * K * C];   // prototypes / (count * ||proto||)
__device__ int   g_counts[B * (K + 1)]; // per-class pixel counts (incl. class 0)
__device__ int   g_mask_idx;            // which input pointer is the mask (0/1/2)

// ---------------------------------------------------------------------------
// Pointer selection: the mask tensor is identified at runtime on-device.
//   mask@1 -> insertion order   [sfeat, mask, qfeat]
//   mask@2 -> alphabetical      [qfeat, sfeat, mask]
//   mask@0 -> fallback          [mask, qfeat, sfeat]
// ---------------------------------------------------------------------------
__device__ __forceinline__ void select_ptrs(
        const void* p0, const void* p1, const void* p2,
        const float*& sf, const int*& mk, const float*& qf) {
    const int m = g_mask_idx;
    const void* P[3] = { p0, p1, p2 };
    mk = (const int*)P[m];
    if (m == 1)      { sf = (const float*)P[0]; qf = (const float*)P[2]; }
    else if (m == 2) { sf = (const float*)P[1]; qf = (const float*)P[0]; }
    else             { sf = (const float*)P[2]; qf = (const float*)P[1]; }
}

// ---------------------------------------------------------------------------
// K0: identify the mask input.  int32 mask values lie in [0,16]; fp32 N(0,1)
// bit patterns interpreted as int essentially never do.  Pick the candidate
// with the most in-range samples (robust to any single bad sample).
// ---------------------------------------------------------------------------
__global__ void detect_kernel(const void* p0, const void* p1, const void* p2) {
    if (threadIdx.x != 0 || blockIdx.x != 0) return;
    const int* cand[3] = { (const int*)p0, (const int*)p1, (const int*)p2 };
    int best = 1, best_hits = -1;
    for (int i = 0; i < 3; i++) {
        const int* p = cand[i];
        int hits = 0;
        for (int j = 0; j < 1024; j++) {
            int v = p[j * 17 + 3];           // max index 17397 < 32768
            if (v >= 0 && v <= K) hits++;
        }
        if (hits > best_hits) { best_hits = hits; best = i; }
    }
    g_mask_idx = best;
}

// ---------------------------------------------------------------------------
// K1: per-batch class histogram of the support mask
// ---------------------------------------------------------------------------
__global__ void __launch_bounds__(256) hist_kernel(
        const void* p0, const void* p1, const void* p2) {
    const float* sf; const int* masks; const float* qf;
    select_ptrs(p0, p1, p2, sf, masks, qf);

    __shared__ int h[K + 1];
    const int b   = blockIdx.x;
    const int tid = threadIdx.x;
    if (tid <= K) h[tid] = 0;
    __syncthreads();
    for (int p = tid; p < HW; p += 256) {
        int v = masks[b * HW + p];
        if (v >= 0 && v <= K) atomicAdd(&h[v], 1);   // guarded: never traps
    }
    __syncthreads();
    if (tid <= K) g_counts[b * (K + 1) + tid] = h[tid];
}

// ---------------------------------------------------------------------------
// K2: masked per-class sums.  One warp = one channel.  Each lane accumulates
// into private shared slots acc[class][tid]; bank = tid%32 for any class, so
// the dynamic class index is bank-conflict-free and avoids the 16x
// compare-add ALU cost of a static-index formulation.
// ---------------------------------------------------------------------------
__global__ void __launch_bounds__(256) proto_sum_kernel(
        const void* p0, const void* p1, const void* p2) {
    const float* feat; const int* masks; const float* qf;
    select_ptrs(p0, p1, p2, feat, masks, qf);

    __shared__ unsigned char cls[HW];       // 4 KB
    __shared__ float acc[K][256];           // 16 KB, conflict-free layout

    const int b    = blockIdx.y;
    const int tid  = threadIdx.x;
    const int warp = tid >> 5;
    const int lane = tid & 31;
    const int c    = blockIdx.x * 8 + warp;

#pragma unroll
    for (int k = 0; k < K; k++) acc[k][tid] = 0.0f;
    for (int p = tid; p < HW; p += 256) {
        int v = masks[b * HW + p];
        cls[p] = (unsigned char)((v >= 1 && v <= K) ? v : 0);  // guarded
    }
    __syncthreads();

    const float4* f4 = (const float4*)(feat + ((size_t)b * C + c) * HW);
    const uchar4* c4 = (const uchar4*)cls;

    for (int i = lane; i < HW / 4; i += 32) {
        float4 v  = f4[i];     // coalesced 128B per warp
        uchar4 cc = c4[i];
        if (cc.x) acc[cc.x - 1][tid] += v.x;
        if (cc.y) acc[cc.y - 1][tid] += v.y;
        if (cc.z) acc[cc.z - 1][tid] += v.z;
        if (cc.w) acc[cc.w - 1][tid] += v.w;
    }

    // Per-lane partials -> warp sum -> one channel's 16 class sums.
#pragma unroll
    for (int k = 0; k < K; k++) {
        float s = acc[k][tid];
#pragma unroll
        for (int off = 16; off; off >>= 1)
            s += __shfl_down_sync(0xffffffffu, s, off);
        if (lane == 0) g_num[((size_t)b * K + k) * C + c] = s;
    }
}

// ---------------------------------------------------------------------------
// K3: prototypes = num/count;  g_protoN = prototypes / ||prototypes||.
// argmax_k dot(protoN_k, q) == argmax_k cosine_sim (qn > 0 is a common
// factor across k; the eps clamp never binds: pn*qn ~ 66 >> 1e-8).
// ---------------------------------------------------------------------------
__global__ void __launch_bounds__(256) finalize_kernel() {
    const int b = blockIdx.y, k = blockIdx.x, tid = threadIdx.x;
    const int cnt = g_counts[b * (K + 1) + k + 1];
    const float invCnt = cnt > 0 ? 1.0f / (float)cnt : 0.0f;
    const float* num = g_num    + ((size_t)(b * K + k)) * C;
    float*       out = g_protoN + ((size_t)(b * K + k)) * C;

    float pv[4];
    float ss = 0.0f;
#pragma unroll
    for (int j = 0; j < 4; j++) {
        pv[j] = num[tid + j * 256] * invCnt;
        ss += pv[j] * pv[j];
    }

    __shared__ float red[8];
    __shared__ float s_inv;
#pragma unroll
    for (int off = 16; off; off >>= 1)
        ss += __shfl_down_sync(0xffffffffu, ss, off);
    if ((tid & 31) == 0) red[tid >> 5] = ss;
    __syncthreads();
    if (tid == 0) {
        float s = 0.0f;
#pragma unroll
        for (int w = 0; w < 8; w++) s += red[w];
        s_inv = s > 0.0f ? 1.0f / sqrtf(s) : 0.0f;
    }
    __syncthreads();
    const float inv = s_inv;
#pragma unroll
    for (int j = 0; j < 4; j++) out[tid + j * 256] = pv[j] * inv;
}

// ---------------------------------------------------------------------------
// K4: per-pixel 16-way dot + argmax.  Channel-chunked prototypes in 32 KB
// STATIC shared memory: 16 protos x 512 channels per chunk, 2 chunks.
// 2 pixels/thread amortizes the proto LDS: 128 FFMA + 16 LDS.128 + 8 LDG
// per 4 channels per thread.  OUTPUT IS WRITTEN AS float32 (labels 0..15
// are exactly representable) — the harness's __output__ dtype.
// ---------------------------------------------------------------------------
#define CCH 512   // channels per smem chunk

__global__ void __launch_bounds__(256) match_kernel(
        const void* p0, const void* p1, const void* p2, float* __restrict__ out) {
    const float* sf; const int* mk; const float* q;
    select_ptrs(p0, p1, p2, sf, mk, q);

    __shared__ float sp[K][CCH];    // 32 KB static
    const int b   = blockIdx.y;
    const int tid = threadIdx.x;

    const int p0i = blockIdx.x * 512 + tid;       // pixel A
    const int p1i = p0i + 256;                    // pixel B
    const float* qa = q + (size_t)b * C * HW + p0i;
    const float* qb = q + (size_t)b * C * HW + p1i;

    float accA[K], accB[K];
#pragma unroll
    for (int k = 0; k < K; k++) { accA[k] = 0.0f; accB[k] = 0.0f; }

#pragma unroll
    for (int ch = 0; ch < C / CCH; ch++) {
        __syncthreads();
        for (int i = tid; i < K * CCH / 4; i += 256) {
            const int k  = i / (CCH / 4);
            const int cc = i % (CCH / 4);
            ((float4*)&sp[k][0])[cc] =
                ((const float4*)(g_protoN + ((size_t)b * K + k) * C + ch * CCH))[cc];
        }
        __syncthreads();

        const float* qac = qa + (size_t)ch * CCH * HW;
        const float* qbc = qb + (size_t)ch * CCH * HW;
        for (int c = 0; c < CCH; c += 4) {
            const float a0 = qac[(size_t)(c + 0) * HW];
            const float a1 = qac[(size_t)(c + 1) * HW];
            const float a2 = qac[(size_t)(c + 2) * HW];
            const float a3 = qac[(size_t)(c + 3) * HW];
            const float b0 = qbc[(size_t)(c + 0) * HW];
            const float b1 = qbc[(size_t)(c + 1) * HW];
            const float b2 = qbc[(size_t)(c + 2) * HW];
            const float b3 = qbc[(size_t)(c + 3) * HW];
#pragma unroll
            for (int k = 0; k < K; k++) {
                const float4 pk = *(const float4*)&sp[k][c];   // broadcast LDS.128
                accA[k] += a0 * pk.x + a1 * pk.y + a2 * pk.z + a3 * pk.w;
                accB[k] += b0 * pk.x + b1 * pk.y + b2 * pk.z + b3 * pk.w;
            }
        }
    }

    // first-max-wins => matches jnp.argmax tie semantics
    float bestA = accA[0], bestB = accB[0];
    int   iA = 0, iB = 0;
#pragma unroll
    for (int k = 1; k < K; k++) {
        if (accA[k] > bestA) { bestA = accA[k]; iA = k; }
        if (accB[k] > bestB) { bestB = accB[k]; iB = k; }
    }

    out[(size_t)b * HW + p0i] = (float)iA;   // float32 output dtype
    out[(size_t)b * HW + p1i] = (float)iB;
}

// ---------------------------------------------------------------------------
extern "C" void kernel_launch(void* const* d_in, const int* in_sizes, int n_in,
                              void* d_out, int out_size) {
    const void* p0 = d_in[0];
    const void* p1 = d_in[1];
    const void* p2 = (n_in > 2) ? d_in[2] : d_in[1];
    float* out = (float*)d_out;
    (void)in_sizes; (void)out_size;

    detect_kernel<<<1, 32>>>(p0, p1, p2);
    hist_kernel<<<B, 256>>>(p0, p1, p2);
    proto_sum_kernel<<<dim3(C / 8, B), 256>>>(p0, p1, p2);
    finalize_kernel<<<dim3(K, B), 256>>>();
    match_kernel<<<dim3(HW / 512, B), 256>>>(p0, p1, p2, out);
}

// round 5
// speedup vs baseline: 2.3097x; 2.3097x over previous
#include <cuda_runtime.h>

#define B   8
#define C   1024
#define HW  4096
#define K   16

// Scratch (no allocations allowed) — fully rewritten every launch, so graph
// replay is deterministic.
__device__ float g_num[B * K * C];      // masked class sums
__device__ float g_protoN[B * K * C];   // prototypes / (count * ||proto||)
__device__ int   g_counts[B * (K + 1)]; // per-class pixel counts (incl. class 0)

// ---------------------------------------------------------------------------
// K1: per-batch class histogram of the support mask
// ---------------------------------------------------------------------------
__global__ void __launch_bounds__(256) hist_kernel(const int* __restrict__ masks) {
    __shared__ int h[K + 1];
    const int b   = blockIdx.x;
    const int tid = threadIdx.x;
    if (tid <= K) h[tid] = 0;
    __syncthreads();
    for (int p = tid; p < HW; p += 256) {
        int v = masks[b * HW + p];
        if (v >= 0 && v <= K) atomicAdd(&h[v], 1);   // guarded: never traps
    }
    __syncthreads();
    if (tid <= K) g_counts[b * (K + 1) + tid] = h[tid];
}

// ---------------------------------------------------------------------------
// K2: masked per-class sums.  One warp = one channel.  Each lane accumulates
// into private shared slots acc[class][tid]; bank = tid%32 for any class, so
// the dynamic class index is bank-conflict-free.  DRAM-bound (~128 MB read).
// ---------------------------------------------------------------------------
__global__ void __launch_bounds__(256) proto_sum_kernel(
        const float* __restrict__ feat, const int* __restrict__ masks) {
    __shared__ unsigned char cls[HW];       // 4 KB
    __shared__ float acc[K][256];           // 16 KB, conflict-free layout

    const int b    = blockIdx.y;
    const int tid  = threadIdx.x;
    const int warp = tid >> 5;
    const int lane = tid & 31;
    const int c    = blockIdx.x * 8 + warp;

#pragma unroll
    for (int k = 0; k < K; k++) acc[k][tid] = 0.0f;
    for (int p = tid; p < HW; p += 256) {
        int v = masks[b * HW + p];
        cls[p] = (unsigned char)((v >= 1 && v <= K) ? v : 0);  // guarded
    }
    __syncthreads();

    const float4* f4 = (const float4*)(feat + ((size_t)b * C + c) * HW);
    const uchar4* c4 = (const uchar4*)cls;

    for (int i = lane; i < HW / 4; i += 32) {
        float4 v  = f4[i];     // coalesced 128B per warp
        uchar4 cc = c4[i];
        if (cc.x) acc[cc.x - 1][tid] += v.x;
        if (cc.y) acc[cc.y - 1][tid] += v.y;
        if (cc.z) acc[cc.z - 1][tid] += v.z;
        if (cc.w) acc[cc.w - 1][tid] += v.w;
    }

#pragma unroll
    for (int k = 0; k < K; k++) {
        float s = acc[k][tid];
#pragma unroll
        for (int off = 16; off; off >>= 1)
            s += __shfl_down_sync(0xffffffffu, s, off);
        if (lane == 0) g_num[((size_t)b * K + k) * C + c] = s;
    }
}

// ---------------------------------------------------------------------------
// K3: g_protoN = (num/count) / ||num/count||.
// argmax_k dot(protoN_k, q) == argmax_k cosine_sim (qn > 0 common factor,
// eps clamp never binds: pn*qn ~ 66 >> 1e-8).
// ---------------------------------------------------------------------------
__global__ void __launch_bounds__(256) finalize_kernel() {
    const int b = blockIdx.y, k = blockIdx.x, tid = threadIdx.x;
    const int cnt = g_counts[b * (K + 1) + k + 1];
    const float invCnt = cnt > 0 ? 1.0f / (float)cnt : 0.0f;
    const float* num = g_num    + ((size_t)(b * K + k)) * C;
    float*       out = g_protoN + ((size_t)(b * K + k)) * C;

    float pv[4];
    float ss = 0.0f;
#pragma unroll
    for (int j = 0; j < 4; j++) {
        pv[j] = num[tid + j * 256] * invCnt;
        ss += pv[j] * pv[j];
    }

    __shared__ float red[8];
    __shared__ float s_inv;
#pragma unroll
    for (int off = 16; off; off >>= 1)
        ss += __shfl_down_sync(0xffffffffu, ss, off);
    if ((tid & 31) == 0) red[tid >> 5] = ss;
    __syncthreads();
    if (tid == 0) {
        float s = 0.0f;
#pragma unroll
        for (int w = 0; w < 8; w++) s += red[w];
        s_inv = s > 0.0f ? 1.0f / sqrtf(s) : 0.0f;
    }
    __syncthreads();
    const float inv = s_inv;
#pragma unroll
    for (int j = 0; j < 4; j++) out[tid + j * 256] = pv[j] * inv;
}

// ---------------------------------------------------------------------------
// K4: per-pixel 16-way dot + argmax using packed fp32x2 FMA (FFMA2).
// All 16x1024 normalized prototypes staged once in 64 KB dynamic smem.
// 1 pixel/thread, grid = 128 CTAs -> >=2 warps/SMSP chip-wide.
// Per 4-channel iter: 2 mov.b64 packs + 16 LDS.128 + 32 FFMA2 (vs 128 FFMA).
// ---------------------------------------------------------------------------
__global__ void __launch_bounds__(256) match_kernel(
        const float* __restrict__ q, float* __restrict__ out) {
    extern __shared__ float sp[];   // [K][C] = 64 KB dynamic
    const int b   = blockIdx.y;
    const int tid = threadIdx.x;

    const float4* pr4 = (const float4*)(g_protoN + (size_t)b * K * C);
    for (int i = tid; i < K * C / 4; i += 256)
        ((float4*)sp)[i] = pr4[i];
    __syncthreads();

    const int p = blockIdx.x * 256 + tid;
    const float* qb = q + (size_t)b * C * HW + p;

    unsigned long long acc2[K];
#pragma unroll
    for (int k = 0; k < K; k++) acc2[k] = 0ull;

    for (int c = 0; c < C; c += 4) {
        const float q0 = qb[(size_t)(c + 0) * HW];   // coalesced across threads
        const float q1 = qb[(size_t)(c + 1) * HW];
        const float q2 = qb[(size_t)(c + 2) * HW];
        const float q3 = qb[(size_t)(c + 3) * HW];
        unsigned long long q01, q23;
        asm("mov.b64 %0, {%1, %2};" : "=l"(q01) : "f"(q0), "f"(q1));
        asm("mov.b64 %0, {%1, %2};" : "=l"(q23) : "f"(q2), "f"(q3));
#pragma unroll
        for (int k = 0; k < K; k++) {
            const ulonglong2 pk = *(const ulonglong2*)&sp[k * C + c]; // LDS.128 bcast
            asm("fma.rn.f32x2 %0, %1, %2, %0;" : "+l"(acc2[k]) : "l"(q01), "l"(pk.x));
            asm("fma.rn.f32x2 %0, %1, %2, %0;" : "+l"(acc2[k]) : "l"(q23), "l"(pk.y));
        }
    }

    // fold halves, then first-max-wins argmax (jnp.argmax tie semantics)
    float best = -3.0e38f;
    int   bi   = 0;
#pragma unroll
    for (int k = 0; k < K; k++) {
        float lo, hi;
        asm("mov.b64 {%0, %1}, %2;" : "=f"(lo), "=f"(hi) : "l"(acc2[k]));
        const float v = lo + hi;
        if (v > best) { best = v; bi = k; }
    }

    out[(size_t)b * HW + p] = (float)bi;   // float32 output dtype
}

// ---------------------------------------------------------------------------
extern "C" void kernel_launch(void* const* d_in, const int* in_sizes, int n_in,
                              void* d_out, int out_size) {
    // masks is the unique B*HW = 32768-element input; its position fixes the
    // ordering of the two 33.5M-element feature tensors:
    //   masks @ 1 -> [sfeat, masks, qfeat]   (insertion order)
    //   masks @ 2 -> [qfeat, sfeat, masks]   (alphabetical)
    //   masks @ 0 -> [masks, qfeat, sfeat]
    int mask_idx = 1;
    for (int i = 0; i < n_in; i++)
        if (in_sizes[i] == B * HW) { mask_idx = i; break; }

    const int*   masks = (const int*)d_in[mask_idx];
    const float* sfeat;
    const float* qfeat;
    if (mask_idx == 1)      { sfeat = (const float*)d_in[0]; qfeat = (const float*)d_in[2]; }
    else if (mask_idx == 2) { qfeat = (const float*)d_in[0]; sfeat = (const float*)d_in[1]; }
    else                    { qfeat = (const float*)d_in[1]; sfeat = (const float*)d_in[2]; }
    float* out = (float*)d_out;
    (void)out_size;

    hist_kernel<<<B, 256>>>(masks);
    proto_sum_kernel<<<dim3(C / 8, B), 256>>>(sfeat, masks);
    finalize_kernel<<<dim3(K, B), 256>>>();

    static int smem_set = 0;
    if (!smem_set) {
        cudaFuncSetAttribute(match_kernel,
                             cudaFuncAttributeMaxDynamicSharedMemorySize,
                             K * C * (int)sizeof(float));
        smem_set = 1;
    }
    match_kernel<<<dim3(HW / 256, B), 256, K * C * sizeof(float)>>>(qfeat, out);
}

// round 6
// speedup vs baseline: 3.2552x; 1.4094x over previous
#include <cuda_runtime.h>

#define B   8
#define C   1024
#define HW  4096
#define K   16

// Scratch (no allocations allowed) — fully rewritten every launch.
__device__ float g_num[B * K * C];      // masked class sums
__device__ float g_protoN[B * K * C];   // prototypes / (count * ||proto||)
__device__ int   g_counts[B * (K + 1)]; // per-class pixel counts (incl. class 0)

// ---------------------------------------------------------------------------
// K1: per-batch class histogram of the support mask
// ---------------------------------------------------------------------------
__global__ void __launch_bounds__(256) hist_kernel(const int* __restrict__ masks) {
    __shared__ int h[K + 1];
    const int b   = blockIdx.x;
    const int tid = threadIdx.x;
    if (tid <= K) h[tid] = 0;
    __syncthreads();
    for (int p = tid; p < HW; p += 256) {
        int v = masks[b * HW + p];
        if (v >= 0 && v <= K) atomicAdd(&h[v], 1);   // guarded: never traps
    }
    __syncthreads();
    if (tid <= K) g_counts[b * (K + 1) + tid] = h[tid];
}

// ---------------------------------------------------------------------------
// K2: masked per-class sums.  One warp = one channel; lane-private smem slots
// acc[class][tid] (bank = tid%32 for any class -> conflict-free dynamic
// indexing).  DRAM-bound (~128 MB read).
// ---------------------------------------------------------------------------
__global__ void __launch_bounds__(256) proto_sum_kernel(
        const float* __restrict__ feat, const int* __restrict__ masks) {
    __shared__ unsigned char cls[HW];       // 4 KB
    __shared__ float acc[K][256];           // 16 KB

    const int b    = blockIdx.y;
    const int tid  = threadIdx.x;
    const int warp = tid >> 5;
    const int lane = tid & 31;
    const int c    = blockIdx.x * 8 + warp;

#pragma unroll
    for (int k = 0; k < K; k++) acc[k][tid] = 0.0f;
    for (int p = tid; p < HW; p += 256) {
        int v = masks[b * HW + p];
        cls[p] = (unsigned char)((v >= 1 && v <= K) ? v : 0);  // guarded
    }
    __syncthreads();

    const float4* f4 = (const float4*)(feat + ((size_t)b * C + c) * HW);
    const uchar4* c4 = (const uchar4*)cls;

    for (int i = lane; i < HW / 4; i += 32) {
        float4 v  = f4[i];     // coalesced 128B per warp
        uchar4 cc = c4[i];
        if (cc.x) acc[cc.x - 1][tid] += v.x;
        if (cc.y) acc[cc.y - 1][tid] += v.y;
        if (cc.z) acc[cc.z - 1][tid] += v.z;
        if (cc.w) acc[cc.w - 1][tid] += v.w;
    }

#pragma unroll
    for (int k = 0; k < K; k++) {
        float s = acc[k][tid];
#pragma unroll
        for (int off = 16; off; off >>= 1)
            s += __shfl_down_sync(0xffffffffu, s, off);
        if (lane == 0) g_num[((size_t)b * K + k) * C + c] = s;
    }
}

// ---------------------------------------------------------------------------
// K3: g_protoN = (num/count) / ||num/count||.
// argmax_k dot(protoN_k, q) == argmax_k cosine_sim (qn > 0 common factor,
// eps clamp never binds).
// ---------------------------------------------------------------------------
__global__ void __launch_bounds__(256) finalize_kernel() {
    const int b = blockIdx.y, k = blockIdx.x, tid = threadIdx.x;
    const int cnt = g_counts[b * (K + 1) + k + 1];
    const float invCnt = cnt > 0 ? 1.0f / (float)cnt : 0.0f;
    const float* num = g_num    + ((size_t)(b * K + k)) * C;
    float*       out = g_protoN + ((size_t)(b * K + k)) * C;

    float pv[4];
    float ss = 0.0f;
#pragma unroll
    for (int j = 0; j < 4; j++) {
        pv[j] = num[tid + j * 256] * invCnt;
        ss += pv[j] * pv[j];
    }

    __shared__ float red[8];
    __shared__ float s_inv;
#pragma unroll
    for (int off = 16; off; off >>= 1)
        ss += __shfl_down_sync(0xffffffffu, ss, off);
    if ((tid & 31) == 0) red[tid >> 5] = ss;
    __syncthreads();
    if (tid == 0) {
        float s = 0.0f;
#pragma unroll
        for (int w = 0; w < 8; w++) s += red[w];
        s_inv = s > 0.0f ? 1.0f / sqrtf(s) : 0.0f;
    }
    __syncthreads();
    const float inv = s_inv;
#pragma unroll
    for (int j = 0; j < 4; j++) out[tid + j * 256] = pv[j] * inv;
}

// ---------------------------------------------------------------------------
// K4: channel-split match.  512 threads/CTA: thread = (quarter, pix); each
// thread accumulates 256 channels of the 16 dots for one pixel with FFMA2.
// 256 CTAs, 2 resident/SM (64 KB smem, <=64 regs) -> 32 warps/SM, one wave.
// After the main loop the 64 KB proto buffer is reused for the 4-way packed
// cross-quarter reduction (add.rn.f32x2), then a 128-thread argmax.
// ---------------------------------------------------------------------------
__global__ void __launch_bounds__(512, 2) match_kernel(
        const float* __restrict__ q, float* __restrict__ out) {
    extern __shared__ __align__(16) char smem_raw[];
    float*              sp  = (float*)smem_raw;              // [K][C] = 64 KB
    unsigned long long* red = (unsigned long long*)smem_raw; // reused: [512][16]

    const int b   = blockIdx.y;
    const int tid = threadIdx.x;
    const int quarter = tid >> 7;          // 0..3  -> channels [q*256, q*256+256)
    const int pix     = tid & 127;         // 0..127
    const int p       = blockIdx.x * 128 + pix;

    // stage all 16x1024 normalized prototypes
    const float4* pr4 = (const float4*)(g_protoN + (size_t)b * K * C);
    for (int i = tid; i < K * C / 4; i += 512)
        ((float4*)sp)[i] = pr4[i];
    __syncthreads();

    const float* qb  = q + ((size_t)b * C + quarter * 256) * HW + p;
    const float* spq = sp + quarter * 256;

    unsigned long long acc2[K];
#pragma unroll
    for (int k = 0; k < K; k++) acc2[k] = 0ull;

    for (int c = 0; c < 256; c += 8) {
        // 8 independent LDGs in flight per warp (coalesced: lanes = pixels)
        const float q0 = qb[(size_t)(c + 0) * HW];
        const float q1 = qb[(size_t)(c + 1) * HW];
        const float q2 = qb[(size_t)(c + 2) * HW];
        const float q3 = qb[(size_t)(c + 3) * HW];
        const float q4 = qb[(size_t)(c + 4) * HW];
        const float q5 = qb[(size_t)(c + 5) * HW];
        const float q6 = qb[(size_t)(c + 6) * HW];
        const float q7 = qb[(size_t)(c + 7) * HW];
        unsigned long long q01, q23, q45, q67;
        asm("mov.b64 %0, {%1, %2};" : "=l"(q01) : "f"(q0), "f"(q1));
        asm("mov.b64 %0, {%1, %2};" : "=l"(q23) : "f"(q2), "f"(q3));
        asm("mov.b64 %0, {%1, %2};" : "=l"(q45) : "f"(q4), "f"(q5));
        asm("mov.b64 %0, {%1, %2};" : "=l"(q67) : "f"(q6), "f"(q7));
#pragma unroll
        for (int k = 0; k < K; k++) {
            const ulonglong2 pa = *(const ulonglong2*)&spq[k * C + c];     // LDS.128 bcast
            const ulonglong2 pb = *(const ulonglong2*)&spq[k * C + c + 4];
            asm("fma.rn.f32x2 %0, %1, %2, %0;" : "+l"(acc2[k]) : "l"(q01), "l"(pa.x));
            asm("fma.rn.f32x2 %0, %1, %2, %0;" : "+l"(acc2[k]) : "l"(q23), "l"(pa.y));
            asm("fma.rn.f32x2 %0, %1, %2, %0;" : "+l"(acc2[k]) : "l"(q45), "l"(pb.x));
            asm("fma.rn.f32x2 %0, %1, %2, %0;" : "+l"(acc2[k]) : "l"(q67), "l"(pb.y));
        }
    }

    // protos dead -> reuse smem for packed partials: red[(pix*4+quarter)*16+k]
    __syncthreads();
    {
        unsigned long long* dst = red + ((size_t)(pix * 4 + quarter)) * K;
#pragma unroll
        for (int k = 0; k < K; k++) dst[k] = acc2[k];
    }
    __syncthreads();

    // 4-way cross-quarter reduction + fold + first-max-wins argmax
    if (tid < 128) {
        const unsigned long long* r0 = red + ((size_t)(tid * 4 + 0)) * K;
        const unsigned long long* r1 = red + ((size_t)(tid * 4 + 1)) * K;
        const unsigned long long* r2 = red + ((size_t)(tid * 4 + 2)) * K;
        const unsigned long long* r3 = red + ((size_t)(tid * 4 + 3)) * K;
        float best = -3.0e38f;
        int   bi   = 0;
#pragma unroll
        for (int k = 0; k < K; k++) {
            unsigned long long s01, s23, s;
            asm("add.rn.f32x2 %0, %1, %2;" : "=l"(s01) : "l"(r0[k]), "l"(r1[k]));
            asm("add.rn.f32x2 %0, %1, %2;" : "=l"(s23) : "l"(r2[k]), "l"(r3[k]));
            asm("add.rn.f32x2 %0, %1, %2;" : "=l"(s)   : "l"(s01),  "l"(s23));
            float lo, hi;
            asm("mov.b64 {%0, %1}, %2;" : "=f"(lo), "=f"(hi) : "l"(s));
            const float v = lo + hi;
            if (v > best) { best = v; bi = k; }
        }
        out[(size_t)b * HW + blockIdx.x * 128 + tid] = (float)bi;  // f32 output
    }
}

// ---------------------------------------------------------------------------
extern "C" void kernel_launch(void* const* d_in, const int* in_sizes, int n_in,
                              void* d_out, int out_size) {
    // masks is the unique B*HW = 32768-element input; its position fixes the
    // ordering of the two feature tensors.
    int mask_idx = 1;
    for (int i = 0; i < n_in; i++)
        if (in_sizes[i] == B * HW) { mask_idx = i; break; }

    const int*   masks = (const int*)d_in[mask_idx];
    const float* sfeat;
    const float* qfeat;
    if (mask_idx == 1)      { sfeat = (const float*)d_in[0]; qfeat = (const float*)d_in[2]; }
    else if (mask_idx == 2) { qfeat = (const float*)d_in[0]; sfeat = (const float*)d_in[1]; }
    else                    { qfeat = (const float*)d_in[1]; sfeat = (const float*)d_in[2]; }
    float* out = (float*)d_out;
    (void)out_size;

    hist_kernel<<<B, 256>>>(masks);
    proto_sum_kernel<<<dim3(C / 8, B), 256>>>(sfeat, masks);
    finalize_kernel<<<dim3(K, B), 256>>>();

    static int smem_set = 0;
    if (!smem_set) {
        cudaFuncSetAttribute(match_kernel,
                             cudaFuncAttributeMaxDynamicSharedMemorySize,
                             K * C * (int)sizeof(float));
        smem_set = 1;
    }
    match_kernel<<<dim3(HW / 128, B), 512, K * C * sizeof(float)>>>(qfeat, out);
}